// round 6
// baseline (speedup 1.0000x reference)
#include <cuda_runtime.h>

#define NW 10
#define DIM 1024

typedef unsigned long long u64;

// ---- packed f32x2 primitives ----
__device__ __forceinline__ u64 pk(float x, float y) {
    u64 r; asm("mov.b64 %0,{%1,%2};" : "=l"(r) : "f"(x), "f"(y)); return r;
}
__device__ __forceinline__ u64 pkb(float x) { return pk(x, x); }
__device__ __forceinline__ void upk(u64 a, float& x, float& y) {
    asm("mov.b64 {%0,%1},%2;" : "=f"(x), "=f"(y) : "l"(a));
}
__device__ __forceinline__ u64 f2fma(u64 a, u64 b, u64 c) {
    u64 d; asm("fma.rn.f32x2 %0,%1,%2,%3;" : "=l"(d) : "l"(a), "l"(b), "l"(c)); return d;
}
__device__ __forceinline__ u64 f2mul(u64 a, u64 b) {
    u64 d; asm("mul.rn.f32x2 %0,%1,%2;" : "=l"(d) : "l"(a), "l"(b)); return d;
}
__device__ __forceinline__ u64 f2add(u64 a, u64 b) {
    u64 d; asm("add.rn.f32x2 %0,%1,%2;" : "=l"(d) : "l"(a), "l"(b)); return d;
}
__device__ __forceinline__ u64 swp(u64 a) {      // (re,im)->(im,re)
    float x, y; upk(a, x, y); return pk(y, x);
}
__device__ __forceinline__ u64 ldsv(const u64* p) {   // no cross-gate hoisting
    return *(const volatile u64*)p;
}

// =====================================================================
// Layouts (state index i, 10 bits; wire q <-> bit 9-q):
//  P1/P4: i = (p<<6)|u              p bits = i[9:6]  (wires 0-3)
//  P2/P5: i = ((u>>2)<<6)|(p<<2)|(u&3)  p = i[5:2]   (wires 4-7)
//  P3/P6: i = (u<<4)|p              p bits = i[3:0]  (wires 6-9; gates on 8,9)
// u = (warp_in_pair<<5)|lane.
//
// Swizzles (GF(2)-linear; store/load both conflict-free, verified):
//  sigA (remaps 1->2, 4->5): i ^ ((i[8:6])<<2)
//  sigB (remaps 2->3, 5->6): pos9..0 = i9,i5,i4,i3,i2, i8,i7,i6, i1^i5, i0^i4
//  sigC (remap 3->4 + CNOT): i ^ (i[9:5])
// Each address = base(u) ^ Cp with Cp compile-time.
// =====================================================================

// Fused layer-1 gate on p-bit K (8 butterflies).
template<int K>
__device__ __forceinline__ void l1c8(u64* a, const u64* cf) {
    const u64 arr = ldsv(cf + 0), naiai = ldsv(cf + 1), ainai = ldsv(cf + 2);
    const u64 brr = ldsv(cf + 3), nbrbr = ldsv(cf + 4), nbibi = ldsv(cf + 5);
#pragma unroll
    for (int h = 0; h < 8; ++h) {
        const int m0 = ((h >> K) << (K + 1)) | (h & ((1 << K) - 1));
        const int m1 = m0 | (1 << K);
        u64 a0 = a[m0], a1 = a[m1];
        u64 s0 = swp(a0), s1 = swp(a1);
        u64 n0 = f2fma(arr,   a0, f2fma(naiai, s0, f2fma(brr, a1, f2mul(nbibi, s1))));
        u64 n1 = f2fma(nbrbr, a0, f2fma(nbibi, s0, f2fma(arr, a1, f2mul(ainai, s1))));
        a[m0] = n0; a[m1] = n1;
    }
}

// RY gate on p-bit K (8 butterflies).
template<int K>
__device__ __forceinline__ void ryc8(u64* a, const u64* cf) {
    const u64 cc = ldsv(cf + 0), ss = ldsv(cf + 1), nss = ldsv(cf + 2);
#pragma unroll
    for (int h = 0; h < 8; ++h) {
        const int m0 = ((h >> K) << (K + 1)) | (h & ((1 << K) - 1));
        const int m1 = m0 | (1 << K);
        u64 n0 = f2fma(cc, a[m0], f2mul(nss, a[m1]));
        u64 n1 = f2fma(ss, a[m0], f2mul(cc,  a[m1]));
        a[m0] = n0; a[m1] = n1;
    }
}

__global__ __launch_bounds__(128, 6)
void qsa6_kernel(const float* __restrict__ x,
                 const float* __restrict__ rx0,
                 const float* __restrict__ ry0,
                 const float* __restrict__ ry1,
                 float* __restrict__ out)
{
    __shared__ u64 bufA[2][DIM];      // ping
    __shared__ u64 bufB[2][DIM];      // pong
    __shared__ u64 cl1[NW][6];
    __shared__ u64 cry[NW][3];
    __shared__ u64 cw0[4];
    __shared__ float snorm[2][2];
    __shared__ float sacc[2][2][NW];

    const int tid = threadIdx.x;
    if (tid < NW) {
        float s, c, s0, c0, s1, c1;
        sincosf(0.5f * rx0[tid], &s,  &c);
        sincosf(0.5f * ry0[tid], &s0, &c0);
        sincosf(0.5f * ry1[tid], &s1, &c1);
        const float ar =  c0 * c;
        const float ai =  s0 * s;
        const float br = -s0 * c;
        const float bi = -c0 * s;
        cl1[tid][0] = pkb(ar);
        cl1[tid][1] = pk(-ai,  ai);
        cl1[tid][2] = pk( ai, -ai);
        cl1[tid][3] = pkb(br);
        cl1[tid][4] = pkb(-br);
        cl1[tid][5] = pk(-bi, bi);
        cry[tid][0] = pkb(c1);
        cry[tid][1] = pkb(s1);
        cry[tid][2] = pkb(-s1);
        if (tid == 0) {
            cw0[0] = pk( ar,  ai);
            cw0[1] = pk( br,  bi);
            cw0[2] = pk(-br,  bi);
            cw0[3] = pk( ar, -ai);
        }
    }

    const int s    = tid >> 6;          // state-in-block (0/1)
    const int u    = tid & 63;          // thread within state
    const int lane = tid & 31;
    const int wpr  = (u >> 5) & 1;      // warp-in-pair
    const int n    = blockIdx.x * 2 + s;
    u64* bA = bufA[s];
    u64* bB = bufB[s];

    // ---- Load (P1 layout, coalesced) + packed sumsq ----
    u64 a[16];
    const float* xr = x + (size_t)n * DIM;
    u64 sq = 0ull;
#pragma unroll
    for (int p = 0; p < 16; ++p) {
        a[p] = pkb(xr[(p << 6) + u]);
        sq = f2fma(a[p], a[p], sq);
    }
    float sumsq, dmy;
    upk(sq, sumsq, dmy);
#pragma unroll
    for (int off = 16; off; off >>= 1)
        sumsq += __shfl_xor_sync(0xffffffffu, sumsq, off);
    if (lane == 0) snorm[s][wpr] = sumsq;
    __syncthreads();   // coeffs + norm partials visible
    const float inv = 1.f / fmaxf(sqrtf(snorm[s][0] + snorm[s][1]), 1e-12f);

    // ---- P1: L1 wires 0-3 (wire0 special: real input, norm folded) ----
    {
        const u64 pinv = pkb(inv);
        const u64 pa = f2mul(ldsv(cw0 + 0), pinv), pb = f2mul(ldsv(cw0 + 1), pinv);
        const u64 pc = f2mul(ldsv(cw0 + 2), pinv), pd = f2mul(ldsv(cw0 + 3), pinv);
#pragma unroll
        for (int h = 0; h < 8; ++h) {
            u64 a0 = a[h], a1 = a[h + 8];     // both lanes hold raw real value
            a[h]     = f2fma(a0, pa, f2mul(a1, pb));
            a[h + 8] = f2fma(a0, pc, f2mul(a1, pd));
        }
    }
    l1c8<2>(a, cl1[1]);
    l1c8<1>(a, cl1[2]);
    l1c8<0>(a, cl1[3]);

    // ---- Remap 1 (sigA): P1 -> P2, buffer A ----
    // store base = u, Cp = (p<<6)|((p&7)<<2)
    // load  base = ((u>>2)<<6)|(((u>>2)&7)<<2)|(u&3), Cp = p<<2
    {
        const int bs = u;
        const int bl = ((u >> 2) << 6) | (((u >> 2) & 7) << 2) | (u & 3);
#pragma unroll
        for (int p = 0; p < 16; ++p) bA[bs ^ ((p << 6) | ((p & 7) << 2))] = a[p];
        __syncthreads();
#pragma unroll
        for (int p = 0; p < 16; ++p) a[p] = bA[bl ^ (p << 2)];
    }

    // ---- P2: L1 wires 4-7 ----
    l1c8<3>(a, cl1[4]);
    l1c8<2>(a, cl1[5]);
    l1c8<1>(a, cl1[6]);
    l1c8<0>(a, cl1[7]);

    // ---- Remap 2 (sigB): P2 -> P3, buffer B ----
    // store base = ((u&32)<<4)|(u&31)
    //       Cp = (p3<<8)|(p2<<7)|(p1<<6)|(p0<<5)|(p3<<1)|p2
    // load  base = (u5<<9)|(u1<<8)|(u0<<7)|(u4<<4)|(u3<<3)|(u2<<2)|(u1<<1)|u0
    //       Cp = (p3<<6)|(p2<<5)|(p1<<1)|p0
    {
        const int bs = ((u & 32) << 4) | (u & 31);
        const int u0 = u & 1, u1 = (u >> 1) & 1, u2 = (u >> 2) & 1;
        const int u3 = (u >> 3) & 1, u4 = (u >> 4) & 1, u5 = (u >> 5) & 1;
        const int bl = (u5 << 9) | (u1 << 8) | (u0 << 7) | (u4 << 4) |
                       (u3 << 3) | (u2 << 2) | (u1 << 1) | u0;
#pragma unroll
        for (int p = 0; p < 16; ++p) {
            const int p0 = p & 1, p1 = (p >> 1) & 1, p2 = (p >> 2) & 1, p3 = (p >> 3) & 1;
            bB[bs ^ ((p3 << 8) | (p2 << 7) | (p1 << 6) | (p0 << 5) | (p3 << 1) | p2)] = a[p];
        }
        __syncthreads();
#pragma unroll
        for (int p = 0; p < 16; ++p) {
            const int p0 = p & 1, p1 = (p >> 1) & 1, p2 = (p >> 2) & 1, p3 = (p >> 3) & 1;
            a[p] = bB[bl ^ ((p3 << 6) | (p2 << 5) | (p1 << 1) | p0)];
        }
    }

    // ---- P3: L1 wires 8,9 ----
    l1c8<1>(a, cl1[8]);
    l1c8<0>(a, cl1[9]);

    // ---- Remap 3 (sigC + CNOT fold): P3 -> P4, buffer A ----
    // store base = (u<<4)^(u>>1), Cp = p
    // load: addr = sigC(g(j)), j=(p<<6)|u:
    //   ub = u ^ (u>>1) ^ ((u&1)<<8) ^ ((u&1)<<9); base = ub ^ ((ub>>5)&31)
    //   Cp = (p<<6)^(p<<5)^(p<<1)^p
    {
        const int bs = (u << 4) ^ (u >> 1);
#pragma unroll
        for (int p = 0; p < 16; ++p) bA[bs ^ p] = a[p];
        __syncthreads();
        const int ub = u ^ (u >> 1) ^ ((u & 1) << 8) ^ ((u & 1) << 9);
        const int bl = ub ^ ((ub >> 5) & 31);
#pragma unroll
        for (int p = 0; p < 16; ++p)
            a[p] = bA[bl ^ ((p << 6) ^ (p << 5) ^ (p << 1) ^ p)];
    }

    // ---- P4: L2 wires 0-3 ----
    ryc8<3>(a, cry[0]);
    ryc8<2>(a, cry[1]);
    ryc8<1>(a, cry[2]);
    ryc8<0>(a, cry[3]);

    // ---- Remap 4 (sigA): P4 -> P5, buffer B ----
    {
        const int bs = u;
        const int bl = ((u >> 2) << 6) | (((u >> 2) & 7) << 2) | (u & 3);
#pragma unroll
        for (int p = 0; p < 16; ++p) bB[bs ^ ((p << 6) | ((p & 7) << 2))] = a[p];
        __syncthreads();
#pragma unroll
        for (int p = 0; p < 16; ++p) a[p] = bB[bl ^ (p << 2)];
    }

    // ---- P5: L2 wires 4-7 ----
    ryc8<3>(a, cry[4]);
    ryc8<2>(a, cry[5]);
    ryc8<1>(a, cry[6]);
    ryc8<0>(a, cry[7]);

    // ---- Remap 5 (sigB): P5 -> P6, buffer A ----
    {
        const int bs = ((u & 32) << 4) | (u & 31);
        const int u0 = u & 1, u1 = (u >> 1) & 1, u2 = (u >> 2) & 1;
        const int u3 = (u >> 3) & 1, u4 = (u >> 4) & 1, u5 = (u >> 5) & 1;
        const int bl = (u5 << 9) | (u1 << 8) | (u0 << 7) | (u4 << 4) |
                       (u3 << 3) | (u2 << 2) | (u1 << 1) | u0;
#pragma unroll
        for (int p = 0; p < 16; ++p) {
            const int p0 = p & 1, p1 = (p >> 1) & 1, p2 = (p >> 2) & 1, p3 = (p >> 3) & 1;
            bA[bs ^ ((p3 << 8) | (p2 << 7) | (p1 << 6) | (p0 << 5) | (p3 << 1) | p2)] = a[p];
        }
        __syncthreads();
#pragma unroll
        for (int p = 0; p < 16; ++p) {
            const int p0 = p & 1, p1 = (p >> 1) & 1, p2 = (p >> 2) & 1, p3 = (p >> 3) & 1;
            a[p] = bA[bl ^ ((p3 << 6) | (p2 << 5) | (p1 << 1) | p0)];
        }
    }

    // ---- P6: L2 wires 8,9 ----
    ryc8<1>(a, cry[8]);
    ryc8<0>(a, cry[9]);

    // ---- Z expectations. P6 layout: i = (u<<4)|p.
    // wires 6..9 <-> p bits 3..0 (register signs); wires 0..5 <-> u bits 5..0.
    u64 T = 0, W6 = 0, W7 = 0, W8 = 0, W9 = 0;
    const u64 NEG1 = pkb(-1.0f);
#pragma unroll
    for (int p = 0; p < 16; ++p) {
        u64 q = f2mul(a[p], a[p]);                 // (re^2, im^2)
        T = f2add(T, q);
        W6 = (p & 8) ? f2fma(q, NEG1, W6) : f2add(W6, q);
        W7 = (p & 4) ? f2fma(q, NEG1, W7) : f2add(W7, q);
        W8 = (p & 2) ? f2fma(q, NEG1, W8) : f2add(W8, q);
        W9 = (p & 1) ? f2fma(q, NEG1, W9) : f2add(W9, q);
    }
    float vals[10];
    {
        float xx, yy;
        upk(T, xx, yy); float ft = xx + yy;
        vals[0] = wpr         ? -ft : ft;   // wire0: i9 = u5 (warp bit)
        vals[1] = (lane & 16) ? -ft : ft;   // wire1: i8 = u4
        vals[2] = (lane & 8)  ? -ft : ft;
        vals[3] = (lane & 4)  ? -ft : ft;
        vals[4] = (lane & 2)  ? -ft : ft;
        vals[5] = (lane & 1)  ? -ft : ft;   // wire5: i4 = u0
        upk(W6, xx, yy); vals[6] = xx + yy;
        upk(W7, xx, yy); vals[7] = xx + yy;
        upk(W8, xx, yy); vals[8] = xx + yy;
        upk(W9, xx, yy); vals[9] = xx + yy;
    }
#pragma unroll
    for (int off = 16; off; off >>= 1) {
#pragma unroll
        for (int j = 0; j < NW; ++j)
            vals[j] += __shfl_xor_sync(0xffffffffu, vals[j], off);
    }
    if (lane == 0) {
#pragma unroll
        for (int j = 0; j < NW; ++j) sacc[s][wpr][j] = vals[j];
    }
    __syncthreads();
    if (u < NW)
        out[(size_t)n * NW + u] = sacc[s][0][u] + sacc[s][1][u];
}

extern "C" void kernel_launch(void* const* d_in, const int* in_sizes, int n_in,
                              void* d_out, int out_size) {
    const float* x   = (const float*)d_in[0];
    const float* rx0 = (const float*)d_in[1];
    const float* ry0 = (const float*)d_in[2];
    const float* ry1 = (const float*)d_in[3];
    float* out = (float*)d_out;
    const int n_states = in_sizes[0] / DIM;   // 4096
    qsa6_kernel<<<n_states / 2, 128>>>(x, rx0, ry0, ry1, out);
}

// round 7
// speedup vs baseline: 1.3070x; 1.3070x over previous
#include <cuda_runtime.h>

#define NW 10
#define DIM 1024
#define WARPS_PER_BLK 4

typedef unsigned long long u64;

// ---- packed f32x2 primitives ----
__device__ __forceinline__ u64 pk(float x, float y) {
    u64 r; asm("mov.b64 %0,{%1,%2};" : "=l"(r) : "f"(x), "f"(y)); return r;
}
__device__ __forceinline__ u64 pkb(float x) { return pk(x, x); }
__device__ __forceinline__ void upk(u64 a, float& x, float& y) {
    asm("mov.b64 {%0,%1},%2;" : "=f"(x), "=f"(y) : "l"(a));
}
__device__ __forceinline__ float hadd(u64 a) {   // horizontal add of packed pair
    float x, y; upk(a, x, y); return x + y;
}
__device__ __forceinline__ u64 f2fma(u64 a, u64 b, u64 c) {
    u64 d; asm("fma.rn.f32x2 %0,%1,%2,%3;" : "=l"(d) : "l"(a), "l"(b), "l"(c)); return d;
}
__device__ __forceinline__ u64 f2mul(u64 a, u64 b) {
    u64 d; asm("mul.rn.f32x2 %0,%1,%2;" : "=l"(d) : "l"(a), "l"(b)); return d;
}
__device__ __forceinline__ u64 f2add(u64 a, u64 b) {
    u64 d; asm("add.rn.f32x2 %0,%1,%2;" : "=l"(d) : "l"(a), "l"(b)); return d;
}
__device__ __forceinline__ u64 swp(u64 a) {      // (re,im)->(im,re)
    float x, y; upk(a, x, y); return pk(y, x);
}
__device__ __forceinline__ u64 ldsv(const u64* p) {   // no cross-gate hoisting
    return *(const volatile u64*)p;
}

// XOR swizzle for conflict-free 32x32 8-byte transpose through shared memory.
__device__ __forceinline__ int swz(int idx) {
    return (idx & 0x3E0) | (((idx >> 5) ^ idx) & 31);
}

// Fused layer-1 gate on register bit K; coefficients loaded (volatile) from shared.
template<int K>
__device__ __forceinline__ void l1c(u64* a, const u64* cf) {
    const u64 arr = ldsv(cf + 0), naiai = ldsv(cf + 1), ainai = ldsv(cf + 2);
    const u64 brr = ldsv(cf + 3), nbrbr = ldsv(cf + 4), nbibi = ldsv(cf + 5);
#pragma unroll
    for (int p = 0; p < 16; ++p) {
        const int m0 = ((p >> K) << (K + 1)) | (p & ((1 << K) - 1));
        const int m1 = m0 | (1 << K);
        u64 a0 = a[m0], a1 = a[m1];
        u64 s0 = swp(a0), s1 = swp(a1);
        u64 n0 = f2fma(arr,   a0, f2fma(naiai, s0, f2fma(brr, a1, f2mul(nbibi, s1))));
        u64 n1 = f2fma(nbrbr, a0, f2fma(nbibi, s0, f2fma(arr, a1, f2mul(ainai, s1))));
        a[m0] = n0; a[m1] = n1;
    }
}

// ============================================================================
// Layer-2 + CNOT are folded into the observable:
//   E_q = cos(t1_q) * <Z_q>_phi  -  sin(t1_q) * <X_q>_phi,   phi = CNOT ring psi
// CNOT ring is GF(2)-linear: phi_i = psi_{g(i)}, g(i)=i^(i>>1)^((i&1)<<8)^((i&1)<<9)
//   <Z_q>_phi = sum_j (-1)^{parity(j & M_b)} |psi_j|^2   (b = 9-q; from g^-1)
//   <X_q>_phi = sum_j Re(psi_j^* psi_{j^m_b}),  m_b = g(1<<b)
// M_b: b=9: 0x1FF; b=8: 0x300; b<=7: 0x3FF ^ ((1<<b)-1)
// m_b: b>=2: 3<<(b-1); b=1: 0x3; b=0: 0x301
// LB layout: j = (t<<5)|r  (t = lane, r = register index)
// ============================================================================

__global__ __launch_bounds__(128, 4)
void qsa7_kernel(const float* __restrict__ x,
                 const float* __restrict__ rx0,
                 const float* __restrict__ ry0,
                 const float* __restrict__ ry1,
                 float* __restrict__ out)
{
    __shared__ u64 buf[WARPS_PER_BLK][DIM];   // 8 KB per warp
    __shared__ u64 cl1[NW][6];                // packed layer-1 coeffs
    __shared__ u64 cw0[4];                    // wire-0 real-input special gate
    __shared__ float cz[NW], cx[NW];          // epilogue combine coeffs

    const int tid = threadIdx.x;
    if (tid < NW) {
        float s, c, s0, c0, s1, c1;
        sincosf(0.5f * rx0[tid], &s,  &c);
        sincosf(0.5f * ry0[tid], &s0, &c0);
        sincosf(0.5f * ry1[tid], &s1, &c1);
        const float ar =  c0 * c;
        const float ai =  s0 * s;
        const float br = -s0 * c;
        const float bi = -c0 * s;
        cl1[tid][0] = pkb(ar);
        cl1[tid][1] = pk(-ai,  ai);
        cl1[tid][2] = pk( ai, -ai);
        cl1[tid][3] = pkb(br);
        cl1[tid][4] = pkb(-br);
        cl1[tid][5] = pk(-bi, bi);
        // layer-2 observable coeffs: cos(theta) = c1^2-s1^2, sin(theta) = 2 c1 s1.
        // X accumulators are half-sums for wires {0,1,2,3,5,6,7,8} (factor 2),
        // full-sums for straddler wires {4,9} (factor 1).
        cz[tid] = c1 * c1 - s1 * s1;
        const float fac = (tid == 4 || tid == 9) ? 1.f : 2.f;
        cx[tid] = -fac * 2.f * c1 * s1;
        if (tid == 0) {
            cw0[0] = pk( ar,  ai);
            cw0[1] = pk( br,  bi);
            cw0[2] = pk(-br,  bi);
            cw0[3] = pk( ar, -ai);
        }
    }
    __syncthreads();

    const int w = tid >> 5;
    const int t = tid & 31;
    const int n = blockIdx.x * WARPS_PER_BLK + w;   // state 0..4095
    u64* sb = buf[w];

    // ---- Load (LA: i=(r<<5)|t) + packed sumsq ----
    u64 a[32];
    const float* xr = x + (size_t)n * DIM;
    u64 sq = 0ull;
#pragma unroll
    for (int r = 0; r < 32; ++r) {
        a[r] = pkb(xr[(r << 5) + t]);
        sq = f2fma(a[r], a[r], sq);
    }
    float sumsq, dmy;
    upk(sq, sumsq, dmy);
#pragma unroll
    for (int off = 16; off; off >>= 1)
        sumsq += __shfl_xor_sync(0xffffffffu, sumsq, off);
    const float inv = 1.f / fmaxf(sqrtf(sumsq), 1e-12f);

    // ---- Phase A: fused layer-1 on wires 0..4 (wire q -> reg bit K=4-q) ----
    {   // wire 0 (K=4), specialized for purely-real input; normalization folded in.
        const u64 pinv = pkb(inv);
        const u64 pa = f2mul(ldsv(cw0 + 0), pinv), pb = f2mul(ldsv(cw0 + 1), pinv);
        const u64 pc = f2mul(ldsv(cw0 + 2), pinv), pd = f2mul(ldsv(cw0 + 3), pinv);
#pragma unroll
        for (int p = 0; p < 16; ++p) {
            u64 a0 = a[p], a1 = a[p + 16];      // both lanes hold the raw real value
            a[p]      = f2fma(a0, pa, f2mul(a1, pb));
            a[p + 16] = f2fma(a0, pc, f2mul(a1, pd));
        }
    }
    l1c<3>(a, cl1[1]);
    l1c<2>(a, cl1[2]);
    l1c<1>(a, cl1[3]);
    l1c<0>(a, cl1[4]);

    // ---- Remap LA -> LB (transpose) ----
    __syncwarp();
#pragma unroll
    for (int r = 0; r < 32; ++r) sb[swz((r << 5) | t)] = a[r];
    __syncwarp();
#pragma unroll
    for (int r = 0; r < 32; ++r) a[r] = sb[swz((t << 5) | r)];

    // ---- Phase B: fused layer-1 on wires 5..9 (wire q -> reg bit K=9-q) ----
    l1c<4>(a, cl1[5]);
    l1c<3>(a, cl1[6]);
    l1c<2>(a, cl1[7]);
    l1c<1>(a, cl1[8]);
    l1c<0>(a, cl1[9]);

    // ======================= Epilogue on psi (LB: j=(t<<5)|r) ================
    const u64 NEG1 = pkb(-1.0f);

    // Z-part: tot + 5 signed r-sums (r-masks 0x10,0x18,0x1C,0x1E,0x1F).
    u64 tot = 0, S10 = 0, S18 = 0, S1C = 0, S1E = 0, S1F = 0;
    // X in-register wires 5..8 (m = 0x18, 0xC, 0x6, 0x3), half-sums.
    u64 X5 = 0, X6 = 0, X7 = 0, X8 = 0;
#pragma unroll
    for (int r = 0; r < 32; ++r) {
        u64 q = f2mul(a[r], a[r]);                 // (re^2, im^2)
        tot = f2add(tot, q);
        S10 = ((r >> 4) & 1)                       ? f2fma(q, NEG1, S10) : f2add(S10, q);
        S18 = ((((r >> 4) ^ (r >> 3))) & 1)        ? f2fma(q, NEG1, S18) : f2add(S18, q);
        S1C = ((((r >> 4) ^ (r >> 3) ^ (r >> 2))) & 1) ? f2fma(q, NEG1, S1C) : f2add(S1C, q);
        S1E = ((((r >> 4) ^ (r >> 3) ^ (r >> 2) ^ (r >> 1))) & 1) ? f2fma(q, NEG1, S1E) : f2add(S1E, q);
        S1F = ((((r >> 4) ^ (r >> 3) ^ (r >> 2) ^ (r >> 1) ^ r)) & 1) ? f2fma(q, NEG1, S1F) : f2add(S1F, q);
        if (!(r & 0x10)) X5 = f2fma(a[r], a[r ^ 0x18], X5);
        if (!(r & 0x08)) X6 = f2fma(a[r], a[r ^ 0x0C], X6);
        if (!(r & 0x04)) X7 = f2fma(a[r], a[r ^ 0x06], X7);
        if (!(r & 0x02)) X8 = f2fma(a[r], a[r ^ 0x03], X8);
    }

    // Straddler X wires: w4 (m=0x30: t^1, r^0x10), w9 (m=0x301: t^0x18, r^1). Full sums.
    u64 X4 = 0, X9 = 0;
#pragma unroll
    for (int r = 0; r < 32; ++r) {
        u64 p4 = __shfl_xor_sync(0xffffffffu, a[r ^ 0x10], 1);
        X4 = f2fma(a[r], p4, X4);
        u64 p9 = __shfl_xor_sync(0xffffffffu, a[r ^ 0x01], 0x18);
        X9 = f2fma(a[r], p9, X9);
    }

    // Collapse LB-side accumulators to scalars.
    const float tot_s = hadd(tot);
    const float s10 = hadd(S10), s18 = hadd(S18), s1C = hadd(S1C);
    const float s1E = hadd(S1E), s1F = hadd(S1F);
    const float x4 = hadd(X4), x5 = hadd(X5), x6 = hadd(X6);
    const float x7 = hadd(X7), x8 = hadd(X8), x9 = hadd(X9);

    // ---- Transpose state LB -> LA for wires 0..3 X-terms ----
    __syncwarp();
#pragma unroll
    for (int r = 0; r < 32; ++r) sb[swz((t << 5) | r)] = a[r];
    __syncwarp();
#pragma unroll
    for (int r = 0; r < 32; ++r) a[r] = sb[swz((r << 5) | t)];

    // X in-register wires 0..3 in LA (partners r^0x18, r^0xC, r^6, r^3), half-sums.
    u64 X0 = 0, X1 = 0, X2 = 0, X3 = 0;
#pragma unroll
    for (int r = 0; r < 32; ++r) {
        if (!(r & 0x10)) X0 = f2fma(a[r], a[r ^ 0x18], X0);
        if (!(r & 0x08)) X1 = f2fma(a[r], a[r ^ 0x0C], X1);
        if (!(r & 0x04)) X2 = f2fma(a[r], a[r ^ 0x06], X2);
        if (!(r & 0x02)) X3 = f2fma(a[r], a[r ^ 0x03], X3);
    }
    const float x0 = hadd(X0), x1 = hadd(X1), x2 = hadd(X2), x3 = hadd(X3);

    // Thread-parity signs for the Z parts (t-masks from M_b >> 5).
    const float sgA = (__popc(t & 0x0F) & 1) ? -1.f : 1.f;   // wire 0
    const float sgB = (__popc(t & 0x18) & 1) ? -1.f : 1.f;   // wire 1
    const float sgC = (__popc(t & 0x1C) & 1) ? -1.f : 1.f;   // wire 2
    const float sgD = (__popc(t & 0x1E) & 1) ? -1.f : 1.f;   // wire 3
    const float sgE = (__popc(t & 0x1F) & 1) ? -1.f : 1.f;   // wires 4..9

    // Combine: E_q = cz[q] * Z_q + cx[q] * X_q  (per-thread partials).
    float e[NW];
    e[0] = cz[0] * (sgA * s1F) + cx[0] * x0;
    e[1] = cz[1] * (sgB * tot_s) + cx[1] * x1;
    e[2] = cz[2] * (sgC * tot_s) + cx[2] * x2;
    e[3] = cz[3] * (sgD * tot_s) + cx[3] * x3;
    e[4] = cz[4] * (sgE * tot_s) + cx[4] * x4;
    e[5] = cz[5] * (sgE * s10) + cx[5] * x5;
    e[6] = cz[6] * (sgE * s18) + cx[6] * x6;
    e[7] = cz[7] * (sgE * s1C) + cx[7] * x7;
    e[8] = cz[8] * (sgE * s1E) + cx[8] * x8;
    e[9] = cz[9] * (sgE * s1F) + cx[9] * x9;

    // Packed warp reduction of 10 values as 5 u64.
    u64 vp[5];
#pragma unroll
    for (int j = 0; j < 5; ++j) vp[j] = pk(e[2 * j], e[2 * j + 1]);
#pragma unroll
    for (int off = 16; off; off >>= 1) {
#pragma unroll
        for (int j = 0; j < 5; ++j)
            vp[j] = f2add(vp[j], __shfl_xor_sync(0xffffffffu, vp[j], off));
    }
    if (t == 0) {
#pragma unroll
        for (int j = 0; j < 5; ++j) {
            float vx, vy;
            upk(vp[j], vx, vy);
            out[(size_t)n * NW + 2 * j]     = vx;
            out[(size_t)n * NW + 2 * j + 1] = vy;
        }
    }
}

extern "C" void kernel_launch(void* const* d_in, const int* in_sizes, int n_in,
                              void* d_out, int out_size) {
    const float* x   = (const float*)d_in[0];
    const float* rx0 = (const float*)d_in[1];
    const float* ry0 = (const float*)d_in[2];
    const float* ry1 = (const float*)d_in[3];
    float* out = (float*)d_out;
    const int n_states = in_sizes[0] / DIM;            // 4096
    qsa7_kernel<<<n_states / WARPS_PER_BLK, 32 * WARPS_PER_BLK>>>(x, rx0, ry0, ry1, out);
}